// round 3
// baseline (speedup 1.0000x reference)
#include <cuda_runtime.h>
#include <cuda_bf16.h>
#include <cstdint>

// HashGridEncoding: P points x L=9 levels, dense multi-res grid, trilinear.
// R2 finding: L1 pipe is bound by miss-sector FILLS, not load instructions.
// Levels >=6 (2.2MB/17MB/135MB tables) have ~zero L1 reuse but thrash the
// heavily-reused level 0-5 lines. Fix: __ldcg (L2-only, no L1 allocation)
// for l>=6, default caching for l<=5.

#define NUM_LEVELS 9

__device__ __forceinline__ float2 ld_tab(const float2* __restrict__ p, bool streaming)
{
    // streaming (l>=6): L2-only, don't allocate/thrash L1.
    // resident (l<=5): normal L1 caching (high reuse).
    return streaming ? __ldcg(p) : __ldg(p);
}

__global__ void __launch_bounds__(288) hashgrid_kernel(
    const float* __restrict__ x,
    const float* __restrict__ table,
    float* __restrict__ out,
    int P)
{
    int tid = blockIdx.x * blockDim.x + threadIdx.x;
    int p = tid / NUM_LEVELS;
    int l = tid - p * NUM_LEVELS;
    if (p >= P) return;

    float px = __ldg(&x[p * 3 + 0]);
    float py = __ldg(&x[p * 3 + 1]);
    float pz = __ldg(&x[p * 3 + 2]);

    int   vi = 1 << l;
    float vf = (float)vi;

    float gx = (px + 1.0f) * 0.5f * vf;
    float gy = (py + 1.0f) * 0.5f * vf;
    float gz = (pz + 1.0f) * 0.5f * vf;

    float bxf = floorf(gx);
    float byf = floorf(gy);
    float bzf = floorf(gz);

    float fx = gx - bxf;
    float fy = gy - byf;
    float fz = gz - bzf;

    int ix = (int)bxf;
    int iy = (int)byf;
    int iz = (int)bzf;

    int flat = ix + iy * vi + iz * vi * vi;
    int dz   = vi * vi;

    const float2* __restrict__ tab = (const float2*)table;
    bool streaming = (l >= 6);

    float2 q000 = ld_tab(tab + flat,               streaming);
    float2 q100 = ld_tab(tab + flat + 1,           streaming);
    float2 q010 = ld_tab(tab + flat + vi,          streaming);
    float2 q110 = ld_tab(tab + flat + vi + 1,      streaming);
    float2 q001 = ld_tab(tab + flat + dz,          streaming);
    float2 q101 = ld_tab(tab + flat + dz + 1,      streaming);
    float2 q011 = ld_tab(tab + flat + dz + vi,     streaming);
    float2 q111 = ld_tab(tab + flat + dz + vi + 1, streaming);

    float wx0 = 1.0f - fx, wx1 = fx;
    float wy0 = 1.0f - fy, wy1 = fy;
    float wz0 = 1.0f - fz, wz1 = fz;

    float a0x = wx0 * q000.x + wx1 * q100.x;
    float a0y = wx0 * q000.y + wx1 * q100.y;
    float a1x = wx0 * q010.x + wx1 * q110.x;
    float a1y = wx0 * q010.y + wx1 * q110.y;
    float a2x = wx0 * q001.x + wx1 * q101.x;
    float a2y = wx0 * q001.y + wx1 * q101.y;
    float a3x = wx0 * q011.x + wx1 * q111.x;
    float a3y = wx0 * q011.y + wx1 * q111.y;

    float b0x = wy0 * a0x + wy1 * a1x;
    float b0y = wy0 * a0y + wy1 * a1y;
    float b1x = wy0 * a2x + wy1 * a3x;
    float b1y = wy0 * a2y + wy1 * a3y;

    float rx = wz0 * b0x + wz1 * b1x;
    float ry = wz0 * b0y + wz1 * b1y;

    float2* __restrict__ o2 = (float2*)out;
    o2[p * NUM_LEVELS + l] = make_float2(rx, ry);
}

extern "C" void kernel_launch(void* const* d_in, const int* in_sizes, int n_in,
                              void* d_out, int out_size)
{
    const float* x     = (const float*)d_in[0];
    const float* table = (const float*)d_in[1];
    float* out         = (float*)d_out;

    int P = in_sizes[0] / 3;
    int total = P * NUM_LEVELS;
    int threads = 288;                 // 32 points per block
    int blocks = (total + threads - 1) / threads;
    hashgrid_kernel<<<blocks, threads>>>(x, table, out, P);
}